// round 1
// baseline (speedup 1.0000x reference)
#include <cuda_runtime.h>
#include <cstdint>

#define N_NODES   50000
#define N_EDGES   400000
#define E_TOT     (N_EDGES + N_NODES)
#define N_GRAPHS  128
#define D_IN      768
#define D_HID     256
#define NEG_SLOPE 0.2f
#define EPS_COS   1e-8f
#define EPS_BN    1e-5f

// ---------------- scratch (device globals; no allocation) ----------------
__device__ float    g_rel[N_NODES];
__device__ float    g_bufA[(size_t)N_NODES * D_HID];
__device__ float    g_bufB[(size_t)N_NODES * D_HID];
__device__ float    g_as[N_NODES];
__device__ float    g_ad[N_NODES];
__device__ unsigned g_maxenc[N_NODES];
__device__ float    g_denom[N_NODES];
__device__ float    g_edge[E_TOT];
__device__ float    g_bnsum[D_HID];
__device__ float    g_bnsq[D_HID];
__device__ float    g_pool[N_GRAPHS * D_HID];
__device__ int      g_cnt[N_GRAPHS];

// ---------------- helpers ----------------
__device__ __forceinline__ float warp_red(float v) {
    #pragma unroll
    for (int o = 16; o; o >>= 1) v += __shfl_xor_sync(0xffffffffu, v, o);
    return v;
}
__device__ __forceinline__ unsigned fenc(float f) {
    unsigned u = __float_as_uint(f);
    return (u & 0x80000000u) ? ~u : (u | 0x80000000u);
}
__device__ __forceinline__ float fdec(unsigned u) {
    return (u & 0x80000000u) ? __uint_as_float(u & 0x7FFFFFFFu)
                             : __uint_as_float(~u);
}

// ---------------- zero kernels ----------------
__global__ void k_zero_nodes(unsigned* maxenc, float* denom) {
    int i = blockIdx.x * blockDim.x + threadIdx.x;
    if (i < N_NODES) { maxenc[i] = 0u; denom[i] = 0.0f; }
}
__global__ void k_zero_misc(float* bnsum, float* bnsq, float* pool, int* cnt) {
    int i = blockIdx.x * blockDim.x + threadIdx.x;
    if (i < N_GRAPHS * D_HID) pool[i] = 0.0f;
    if (i < D_HID) { bnsum[i] = 0.0f; bnsq[i] = 0.0f; }
    if (i < N_GRAPHS) cnt[i] = 0;
}
__global__ void k_zero_big(float4* p) {
    size_t i = (size_t)blockIdx.x * blockDim.x + threadIdx.x;
    if (i < (size_t)N_NODES * (D_HID / 4)) p[i] = make_float4(0.f, 0.f, 0.f, 0.f);
}

// ---------------- relevance (cosine) + graph counts ----------------
__global__ void k_rel(const float* __restrict__ claim, const float* __restrict__ x,
                      const int* __restrict__ batch, float* __restrict__ rel,
                      int* __restrict__ cnt) {
    int warp = (blockIdx.x * blockDim.x + threadIdx.x) >> 5;
    int lane = threadIdx.x & 31;
    if (warp >= N_NODES) return;
    int b = batch[warp];
    const float* ce = claim + (size_t)b * D_IN;
    const float* xv = x + (size_t)warp * D_IN;
    float dot = 0.f, nc = 0.f, nx = 0.f;
    #pragma unroll 4
    for (int k = lane; k < D_IN; k += 32) {
        float c = ce[k], v = xv[k];
        dot += c * v; nc += c * c; nx += v * v;
    }
    dot = warp_red(dot); nc = warp_red(nc); nx = warp_red(nx);
    if (lane == 0) {
        float nrm = sqrtf(nc) * sqrtf(nx);
        rel[warp] = dot / fmaxf(nrm, EPS_COS);
        atomicAdd(&cnt[b], 1);
    }
}

// ---------------- tiled SGEMM: C[M,256] = (rowscale(A)) @ B[K,256] ----------------
#define BM 64
#define BN 64
#define BK 16
__global__ __launch_bounds__(256) void k_gemm(
    const float* __restrict__ A, int K,
    const float* __restrict__ B, float* __restrict__ C,
    const float* __restrict__ scale, int M)
{
    __shared__ float As[BK][BM + 1];
    __shared__ float Bs[BK][BN];
    int tid = threadIdx.x;
    int m0 = blockIdx.x * BM;
    int n0 = blockIdx.y * BN;

    int arow = tid >> 2;            // 0..63
    int acol = (tid & 3) * 4;       // 0,4,8,12
    int brow = tid >> 4;            // 0..15
    int bcol = (tid & 15) * 4;      // 0..60

    int gr = m0 + arow;
    bool rv = gr < M;
    float s = 1.0f;
    if (scale != nullptr && rv) s = scale[gr];

    int tx = tid & 15, ty = tid >> 4;
    float acc[4][4];
    #pragma unroll
    for (int i = 0; i < 4; i++)
        #pragma unroll
        for (int j = 0; j < 4; j++) acc[i][j] = 0.f;

    for (int k0 = 0; k0 < K; k0 += BK) {
        float4 av = rv ? *(const float4*)(A + (size_t)gr * K + k0 + acol)
                       : make_float4(0.f, 0.f, 0.f, 0.f);
        As[acol + 0][arow] = av.x * s;
        As[acol + 1][arow] = av.y * s;
        As[acol + 2][arow] = av.z * s;
        As[acol + 3][arow] = av.w * s;
        float4 bv = *(const float4*)(B + (size_t)(k0 + brow) * D_HID + n0 + bcol);
        *(float4*)&Bs[brow][bcol] = bv;
        __syncthreads();
        #pragma unroll
        for (int k = 0; k < BK; k++) {
            float a0 = As[k][ty * 4 + 0], a1 = As[k][ty * 4 + 1];
            float a2 = As[k][ty * 4 + 2], a3 = As[k][ty * 4 + 3];
            float b0 = Bs[k][tx * 4 + 0], b1 = Bs[k][tx * 4 + 1];
            float b2 = Bs[k][tx * 4 + 2], b3 = Bs[k][tx * 4 + 3];
            acc[0][0] += a0 * b0; acc[0][1] += a0 * b1; acc[0][2] += a0 * b2; acc[0][3] += a0 * b3;
            acc[1][0] += a1 * b0; acc[1][1] += a1 * b1; acc[1][2] += a1 * b2; acc[1][3] += a1 * b3;
            acc[2][0] += a2 * b0; acc[2][1] += a2 * b1; acc[2][2] += a2 * b2; acc[2][3] += a2 * b3;
            acc[3][0] += a3 * b0; acc[3][1] += a3 * b1; acc[3][2] += a3 * b2; acc[3][3] += a3 * b3;
        }
        __syncthreads();
    }
    #pragma unroll
    for (int i = 0; i < 4; i++) {
        int r = m0 + ty * 4 + i;
        if (r < M) {
            float4 o = make_float4(acc[i][0], acc[i][1], acc[i][2], acc[i][3]);
            *(float4*)(C + (size_t)r * D_HID + n0 + tx * 4) = o;
        }
    }
}

// ---------------- per-node attention coefficients ----------------
__global__ void k_alpha(const float* __restrict__ h,
                        const float* __restrict__ a_s, const float* __restrict__ a_d,
                        float* __restrict__ os, float* __restrict__ od) {
    int warp = (blockIdx.x * blockDim.x + threadIdx.x) >> 5;
    int lane = threadIdx.x & 31;
    if (warp >= N_NODES) return;
    const float* hr = h + (size_t)warp * D_HID;
    float s = 0.f, d = 0.f;
    #pragma unroll
    for (int j = lane; j < D_HID; j += 32) {
        float v = hr[j];
        s += v * a_s[j];
        d += v * a_d[j];
    }
    s = warp_red(s); d = warp_red(d);
    if (lane == 0) { os[warp] = s; od[warp] = d; }
}

// ---------------- edge pass 1: leaky-relu score + segment max ----------------
__global__ void k_edge_max(const int* __restrict__ ei,
                           const float* __restrict__ as, const float* __restrict__ ad,
                           float* __restrict__ edge, unsigned* __restrict__ maxenc) {
    int i = blockIdx.x * blockDim.x + threadIdx.x;
    if (i >= E_TOT) return;
    int s, d;
    if (i < N_EDGES) { s = ei[i]; d = ei[N_EDGES + i]; }
    else { s = d = i - N_EDGES; }
    float e = as[s] + ad[d];
    e = (e > 0.f) ? e : NEG_SLOPE * e;
    edge[i] = e;
    atomicMax(&maxenc[d], fenc(e));
}

// ---------------- edge pass 2: exp + segment sum ----------------
__global__ void k_edge_exp(const int* __restrict__ ei,
                           float* __restrict__ edge,
                           const unsigned* __restrict__ maxenc,
                           float* __restrict__ denom) {
    int i = blockIdx.x * blockDim.x + threadIdx.x;
    if (i >= E_TOT) return;
    int d = (i < N_EDGES) ? ei[N_EDGES + i] : (i - N_EDGES);
    float ex = expf(edge[i] - fdec(maxenc[d]));
    edge[i] = ex;
    atomicAdd(&denom[d], ex);
}

// ---------------- edge pass 3: weighted aggregation (warp/edge, v4 red) ----------------
__global__ void k_agg(const float* __restrict__ h, float* __restrict__ agg,
                      const int* __restrict__ ei, const float* __restrict__ edge,
                      const float* __restrict__ denom) {
    int i = (int)(((size_t)blockIdx.x * blockDim.x + threadIdx.x) >> 5);
    int lane = threadIdx.x & 31;
    if (i >= E_TOT) return;
    int s, d;
    if (i < N_EDGES) { s = ei[i]; d = ei[N_EDGES + i]; }
    else { s = d = i - N_EDGES; }
    float attn = edge[i] / denom[d];
    const float4* hs = (const float4*)(h + (size_t)s * D_HID);
    float4* od = (float4*)(agg + (size_t)d * D_HID);
    #pragma unroll
    for (int j = 0; j < 2; j++) {
        int c = lane + j * 32;
        float4 v = hs[c];
        asm volatile("red.global.add.v4.f32 [%0], {%1,%2,%3,%4};"
                     :: "l"(od + c),
                        "f"(v.x * attn), "f"(v.y * attn), "f"(v.z * attn), "f"(v.w * attn)
                     : "memory");
    }
}

// ---------------- BatchNorm stats ----------------
#define ROWS_PER_BLK 64
__global__ void k_bnstats(const float* __restrict__ h, float* __restrict__ bsum,
                          float* __restrict__ bsq) {
    int col = threadIdx.x;
    int r0 = blockIdx.x * ROWS_PER_BLK;
    int r1 = min(r0 + ROWS_PER_BLK, N_NODES);
    float s = 0.f, q = 0.f;
    for (int r = r0; r < r1; r++) {
        float v = h[(size_t)r * D_HID + col];
        s += v; q += v * v;
    }
    atomicAdd(&bsum[col], s);
    atomicAdd(&bsq[col], q);
}

// ---------------- BatchNorm apply + ReLU ----------------
__global__ void k_bnapply(const float* __restrict__ in, float* __restrict__ out,
                          const float* __restrict__ bsum, const float* __restrict__ bsq,
                          const float* __restrict__ gamma, const float* __restrict__ beta) {
    int col = threadIdx.x;
    float mu = bsum[col] * (1.0f / N_NODES);
    float var = bsq[col] * (1.0f / N_NODES) - mu * mu;
    float sc = gamma[col] * rsqrtf(var + EPS_BN);
    float sh = beta[col] - mu * sc;
    int r0 = blockIdx.x * ROWS_PER_BLK;
    int r1 = min(r0 + ROWS_PER_BLK, N_NODES);
    for (int r = r0; r < r1; r++) {
        float v = in[(size_t)r * D_HID + col];
        out[(size_t)r * D_HID + col] = fmaxf(v * sc + sh, 0.f);
    }
}

// ---------------- pool: relu(h + b2) summed per graph ----------------
__global__ void k_pool(const float* __restrict__ h, const float* __restrict__ b2,
                       const int* __restrict__ batch, float* __restrict__ pool) {
    int col = threadIdx.x;
    float bb = b2[col];
    int r0 = blockIdx.x * ROWS_PER_BLK;
    int r1 = min(r0 + ROWS_PER_BLK, N_NODES);
    int cur = -1;
    float acc = 0.f;
    for (int r = r0; r < r1; r++) {
        int g = batch[r];
        float v = fmaxf(h[(size_t)r * D_HID + col] + bb, 0.f);
        if (g != cur) {
            if (cur >= 0) atomicAdd(&pool[cur * D_HID + col], acc);
            cur = g; acc = v;
        } else acc += v;
    }
    if (cur >= 0) atomicAdd(&pool[cur * D_HID + col], acc);
}

// ---------------- classifier ----------------
__global__ void k_clf(const float* __restrict__ pool, const int* __restrict__ cnt,
                      const float* __restrict__ claim, const float* __restrict__ W,
                      const float* __restrict__ bias, float* __restrict__ out) {
    __shared__ float red[256];
    int b = blockIdx.x;
    int t = threadIdx.x;
    float c = fmaxf((float)cnt[b], 1.0f);
    float part = (pool[b * D_HID + t] / c) * W[t];
    #pragma unroll
    for (int j = 0; j < 3; j++) {
        int k = t + j * 256;
        part += claim[(size_t)b * D_IN + k] * W[D_HID + k];
    }
    red[t] = part;
    __syncthreads();
    #pragma unroll
    for (int o = 128; o; o >>= 1) {
        if (t < o) red[t] += red[t + o];
        __syncthreads();
    }
    if (t == 0) out[b] = red[0] + bias[0];
}

// ---------------- host launcher ----------------
extern "C" void kernel_launch(void* const* d_in, const int* in_sizes, int n_in,
                              void* d_out, int out_size) {
    const float* claim   = (const float*)d_in[0];
    const float* x       = (const float*)d_in[1];
    const int*   ei      = (const int*)d_in[2];
    const int*   batch   = (const int*)d_in[3];
    const float* W1      = (const float*)d_in[4];
    const float* a_src1  = (const float*)d_in[5];
    const float* a_dst1  = (const float*)d_in[6];
    // d_in[7] = b1 : provably no-op through training-mode BatchNorm
    const float* W2      = (const float*)d_in[8];
    const float* a_src2  = (const float*)d_in[9];
    const float* a_dst2  = (const float*)d_in[10];
    const float* b2      = (const float*)d_in[11];
    const float* gamma   = (const float*)d_in[12];
    const float* beta    = (const float*)d_in[13];
    const float* clfW    = (const float*)d_in[14];
    const float* clfb    = (const float*)d_in[15];
    float* out = (float*)d_out;

    float *p_rel, *p_A, *p_B, *p_as, *p_ad, *p_denom, *p_edge, *p_bnsum, *p_bnsq, *p_pool;
    unsigned* p_maxenc;
    int* p_cnt;
    cudaGetSymbolAddress((void**)&p_rel, g_rel);
    cudaGetSymbolAddress((void**)&p_A, g_bufA);
    cudaGetSymbolAddress((void**)&p_B, g_bufB);
    cudaGetSymbolAddress((void**)&p_as, g_as);
    cudaGetSymbolAddress((void**)&p_ad, g_ad);
    cudaGetSymbolAddress((void**)&p_maxenc, g_maxenc);
    cudaGetSymbolAddress((void**)&p_denom, g_denom);
    cudaGetSymbolAddress((void**)&p_edge, g_edge);
    cudaGetSymbolAddress((void**)&p_bnsum, g_bnsum);
    cudaGetSymbolAddress((void**)&p_bnsq, g_bnsq);
    cudaGetSymbolAddress((void**)&p_pool, g_pool);
    cudaGetSymbolAddress((void**)&p_cnt, g_cnt);

    const int nodeBlocks = (N_NODES + 255) / 256;
    const int edgeBlocks = (E_TOT + 255) / 256;
    const int warpNodeBlocks = (N_NODES * 32 + 255) / 256;
    const int warpEdgeBlocks = (int)(((size_t)E_TOT * 32 + 255) / 256);
    const int bigBlocks = (int)(((size_t)N_NODES * (D_HID / 4) + 255) / 256);
    const int chunkBlocks = (N_NODES + ROWS_PER_BLK - 1) / ROWS_PER_BLK;

    // ---- init ----
    k_zero_nodes<<<nodeBlocks, 256>>>(p_maxenc, p_denom);
    k_zero_misc<<<(N_GRAPHS * D_HID + 255) / 256, 256>>>(p_bnsum, p_bnsq, p_pool, p_cnt);
    k_zero_big<<<bigBlocks, 256>>>((float4*)p_B);

    // ---- relevance scaling + counts ----
    k_rel<<<warpNodeBlocks, 256>>>(claim, x, batch, p_rel, p_cnt);

    // ---- layer 1: GAT ----
    {
        dim3 g((N_NODES + BM - 1) / BM, D_HID / BN);
        k_gemm<<<g, 256>>>(x, D_IN, W1, p_A, p_rel, N_NODES);
    }
    k_alpha<<<warpNodeBlocks, 256>>>(p_A, a_src1, a_dst1, p_as, p_ad);
    k_edge_max<<<edgeBlocks, 256>>>(ei, p_as, p_ad, p_edge, p_maxenc);
    k_edge_exp<<<edgeBlocks, 256>>>(ei, p_edge, p_maxenc, p_denom);
    k_agg<<<warpEdgeBlocks, 256>>>(p_A, p_B, ei, p_edge, p_denom);

    // ---- BN + ReLU (b1 cancels exactly in training-mode BN) ----
    k_bnstats<<<chunkBlocks, 256>>>(p_B, p_bnsum, p_bnsq);
    k_bnapply<<<chunkBlocks, 256>>>(p_B, p_A, p_bnsum, p_bnsq, gamma, beta);

    // ---- layer 2: GAT ----
    {
        dim3 g((N_NODES + BM - 1) / BM, D_HID / BN);
        k_gemm<<<g, 256>>>(p_A, D_HID, W2, p_B, nullptr, N_NODES);
    }
    k_alpha<<<warpNodeBlocks, 256>>>(p_B, a_src2, a_dst2, p_as, p_ad);
    k_zero_nodes<<<nodeBlocks, 256>>>(p_maxenc, p_denom);
    k_zero_big<<<bigBlocks, 256>>>((float4*)p_A);
    k_edge_max<<<edgeBlocks, 256>>>(ei, p_as, p_ad, p_edge, p_maxenc);
    k_edge_exp<<<edgeBlocks, 256>>>(ei, p_edge, p_maxenc, p_denom);
    k_agg<<<warpEdgeBlocks, 256>>>(p_B, p_A, ei, p_edge, p_denom);

    // ---- pool + classifier ----
    k_pool<<<chunkBlocks, 256>>>(p_A, b2, batch, p_pool);
    k_clf<<<N_GRAPHS, 256>>>(p_pool, p_cnt, claim, clfW, clfb, out);
}

// round 3
// speedup vs baseline: 1.7369x; 1.7369x over previous
#include <cuda_runtime.h>
#include <cuda_bf16.h>
#include <cstdint>

#define N_NODES   50000
#define N_EDGES   400000
#define E_TOT     (N_EDGES + N_NODES)
#define N_GRAPHS  128
#define D_IN      768
#define D_HID     256
#define NEG_SLOPE 0.2f
#define EPS_COS   1e-8f
#define EPS_BN    1e-5f

// arch-specific (sm_103a) feature gate: tcgen05 only exists in the 'a' target.
// The harness also assembles a plain compute_103 PTX pass; that pass gets a
// correct scalar fallback (never selected at runtime on GB300).
#if defined(__CUDA_ARCH_FEAT_SM103_ALL) || defined(__CUDA_ARCH_SPECIFIC__)
#define HAS_TCGEN05 1
#else
#define HAS_TCGEN05 0
#endif

// ---------------- scratch (device globals; no allocation) ----------------
__device__ float    g_rel[N_NODES];
__device__ float    g_bufA[(size_t)N_NODES * D_HID];
__device__ float    g_bufB[(size_t)N_NODES * D_HID];
__device__ float    g_as[N_NODES];
__device__ float    g_ad[N_NODES];
__device__ unsigned g_maxenc[N_NODES];
__device__ float    g_denom[N_NODES];
__device__ float    g_edge[E_TOT];
__device__ float    g_bnsum[D_HID];
__device__ float    g_bnsq[D_HID];
__device__ float    g_pool[N_GRAPHS * D_HID];
__device__ int      g_cnt[N_GRAPHS];
// pre-swizzled bf16 hi/lo weight images: [ktile][256 n-rows][128 bytes]
__device__ unsigned char g_w1h[12 * 32768];
__device__ unsigned char g_w1l[12 * 32768];
__device__ unsigned char g_w2h[4 * 32768];
__device__ unsigned char g_w2l[4 * 32768];

// ---------------- PTX helpers ----------------
__device__ __forceinline__ uint32_t elect_one_pred() {
    uint32_t pred;
    asm volatile(
        "{\n\t.reg .pred p;\n\t"
        "elect.sync _|p, 0xFFFFFFFF;\n\t"
        "selp.b32 %0, 1, 0, p;\n\t}"
        : "=r"(pred));
    return pred;
}
__device__ __forceinline__ uint32_t smem_to_u32(const void* p) {
    uint32_t a;
    asm("{ .reg .u64 t; cvta.to.shared.u64 t, %1; cvt.u32.u64 %0, t; }"
        : "=r"(a) : "l"(p));
    return a;
}
#define MBARRIER_INIT(addr, cnt) \
    asm volatile("mbarrier.init.shared.b64 [%0], %1;" :: "r"((uint32_t)(addr)), "r"((uint32_t)(cnt)) : "memory")
#define MBARRIER_WAIT_PARITY(addr, parity) do { \
    uint32_t _m = (uint32_t)(addr); uint32_t _p = (uint32_t)(parity); uint32_t _d; \
    asm volatile("{\n\t.reg .pred p;\n\t" \
        "mbarrier.try_wait.parity.acquire.cta.shared::cta.b64 p, [%1], %2;\n\t" \
        "selp.b32 %0, 1, 0, p;\n\t}" : "=r"(_d) : "r"(_m), "r"(_p) : "memory"); \
    if (!_d) { \
        asm volatile("{\n\t.reg .pred P1;\n\t" \
            "WL_%=:\n\t" \
            "mbarrier.try_wait.parity.acquire.cta.shared::cta.b64 P1, [%0], %1, 0x989680;\n\t" \
            "@P1 bra.uni WD_%=;\n\t" \
            "bra.uni WL_%=;\n\t" \
            "WD_%=:\n\t}" :: "r"(_m), "r"(_p) : "memory"); \
    } \
} while (0)
#define TCGEN05_ALLOC(sa, n) \
    asm volatile("tcgen05.alloc.cta_group::1.sync.aligned.shared::cta.b32 [%0], %1;" \
        :: "r"((uint32_t)(sa)), "r"((uint32_t)(n)) : "memory")
#define TCGEN05_DEALLOC(t, n) \
    asm volatile("tcgen05.dealloc.cta_group::1.sync.aligned.b32 %0, %1;" :: "r"(t), "r"((uint32_t)(n)))
#define TCGEN05_RELINQ() \
    asm volatile("tcgen05.relinquish_alloc_permit.cta_group::1.sync.aligned;")
#define TCGEN05_COMMIT(mb) \
    asm volatile("tcgen05.commit.cta_group::1.mbarrier::arrive::one.shared::cluster.b64 [%0];" \
        :: "r"((uint32_t)(mb)) : "memory")
#define TCGEN05_FENCE_AFTER()  asm volatile("tcgen05.fence::after_thread_sync;" ::: "memory")
#define TCGEN05_FENCE_BEFORE() asm volatile("tcgen05.fence::before_thread_sync;" ::: "memory")
#define TCGEN05_WAIT_LD()      asm volatile("tcgen05.wait::ld.sync.aligned;" ::: "memory")
#define FENCE_ASYNC_SHARED()   asm volatile("fence.proxy.async.shared::cta;" ::: "memory")
#define TCGEN05_LD_X32(r, ta) \
    asm volatile("tcgen05.ld.sync.aligned.32x32b.x32.b32 " \
        "{%0, %1, %2, %3, %4, %5, %6, %7, %8, %9, %10, %11, %12, %13, %14, %15, " \
        " %16, %17, %18, %19, %20, %21, %22, %23, %24, %25, %26, %27, %28, %29, %30, %31}, [%32];" \
        : "=r"((r)[0]), "=r"((r)[1]), "=r"((r)[2]), "=r"((r)[3]), \
          "=r"((r)[4]), "=r"((r)[5]), "=r"((r)[6]), "=r"((r)[7]), \
          "=r"((r)[8]), "=r"((r)[9]), "=r"((r)[10]), "=r"((r)[11]), \
          "=r"((r)[12]), "=r"((r)[13]), "=r"((r)[14]), "=r"((r)[15]), \
          "=r"((r)[16]), "=r"((r)[17]), "=r"((r)[18]), "=r"((r)[19]), \
          "=r"((r)[20]), "=r"((r)[21]), "=r"((r)[22]), "=r"((r)[23]), \
          "=r"((r)[24]), "=r"((r)[25]), "=r"((r)[26]), "=r"((r)[27]), \
          "=r"((r)[28]), "=r"((r)[29]), "=r"((r)[30]), "=r"((r)[31]) \
        : "r"(ta))

static constexpr uint64_t SMEM_DESC_BASE_SW128 =
    (uint64_t(2) << 61) | (uint64_t(1) << 46) | (uint64_t(64) << 32) | (uint64_t(1) << 16);
__device__ __forceinline__ uint64_t make_desc(uint32_t addr) {
    return SMEM_DESC_BASE_SW128 | ((uint64_t)(addr >> 4) & 0x3FFF);
}
// idesc: dtype=F32, atype=btype=BF16, N=128, M=128
#define IDESC_G 0x8200490u

#if HAS_TCGEN05
__device__ __forceinline__ void mma_f16_ss(uint32_t d, uint64_t ad, uint64_t bd,
                                           uint32_t idesc, uint32_t en) {
    asm volatile(
        "{\n\t.reg .pred p;\n\t"
        "setp.ne.u32 p, %5, 0;\n\t"
        "tcgen05.mma.cta_group::1.kind::f16 [%0], %1, %2, %3, {%4, %4, %4, %4}, p;\n\t}"
        :: "r"(d), "l"(ad), "l"(bd), "r"(idesc), "r"(0u), "r"(en) : "memory");
}
#endif

__device__ __forceinline__ float warp_red(float v) {
    #pragma unroll
    for (int o = 16; o; o >>= 1) v += __shfl_xor_sync(0xffffffffu, v, o);
    return v;
}
__device__ __forceinline__ unsigned fenc(float f) {
    unsigned u = __float_as_uint(f);
    return (u & 0x80000000u) ? ~u : (u | 0x80000000u);
}
__device__ __forceinline__ float fdec(unsigned u) {
    return (u & 0x80000000u) ? __uint_as_float(u & 0x7FFFFFFFu) : __uint_as_float(~u);
}
__device__ __forceinline__ uint32_t pack_bf(__nv_bfloat16 a, __nv_bfloat16 b) {
    return (uint32_t)__bfloat16_as_ushort(a) | ((uint32_t)__bfloat16_as_ushort(b) << 16);
}

// ---------------- weight prep: fp32 [K,256] -> pre-swizzled bf16 hi/lo ----------------
__global__ void k_prep_w(const float* __restrict__ W, int K,
                         unsigned char* __restrict__ hi, unsigned char* __restrict__ lo) {
    int idx = blockIdx.x * blockDim.x + threadIdx.x;
    if (idx >= K * 256) return;
    int k = idx >> 8, n = idx & 255;
    float v = W[idx];
    __nv_bfloat16 h = __float2bfloat16_rn(v);
    __nv_bfloat16 l = __float2bfloat16_rn(v - __bfloat162float(h));
    int kt = k >> 6, kk = k & 63;
    uint32_t off = (uint32_t)(n * 128 + kk * 2);
    off ^= ((off >> 3) & 0x70);
    size_t base = (size_t)kt * 32768 + off;
    *(__nv_bfloat16*)(hi + base) = h;
    *(__nv_bfloat16*)(lo + base) = l;
}

// ---------------- tcgen05 GEMM: C[M,256] = rowscale(A[M,K]) @ W[K,256] ----------------
// SMEM layout
#define SM_TPTR 0
#define SM_MBAR 8
#define SM_AH   1024
#define SM_AL   (1024 + 16384)
#define SM_BH   33792
#define SM_BL   66560
#define SM_SZ   99328

__global__ __launch_bounds__(128) void k_gemm_tc(
    const float* __restrict__ A, int K,
    const unsigned char* __restrict__ Bh, const unsigned char* __restrict__ Bl,
    float* __restrict__ C, const float* __restrict__ scale, int M)
{
#if HAS_TCGEN05
    extern __shared__ char smem[];
    uint32_t sb = smem_to_u32(smem);
    int tid = threadIdx.x, wid = tid >> 5, lane = tid & 31;
    int m0 = blockIdx.x * 128;

    if (tid == 0) MBARRIER_INIT(sb + SM_MBAR, 1);
    if (wid == 0) TCGEN05_ALLOC(sb + SM_TPTR, 256);
    __syncthreads();
    uint32_t tmem;
    asm volatile("ld.shared.b32 %0, [%1];" : "=r"(tmem) : "r"(sb + SM_TPTR));
    if (wid == 0) TCGEN05_RELINQ();

    const uint64_t aH = make_desc(sb + SM_AH);
    const uint64_t aL = make_desc(sb + SM_AL);
    const uint64_t bH = make_desc(sb + SM_BH);
    const uint64_t bL = make_desc(sb + SM_BL);

    int rbase = tid >> 4;        // 0..7
    int cq = (tid & 15) << 2;    // 0,4,...,60
    int ph = 0;
    const int nk = K >> 6;

    for (int kt = 0; kt < nk; kt++) {
        if (kt) { MBARRIER_WAIT_PARITY(sb + SM_MBAR, ph); ph ^= 1; }
        int k0 = kt << 6;
        // ---- A tile: load fp32, row-scale, split to bf16 hi/lo, STS swizzled ----
        #pragma unroll
        for (int i = 0; i < 16; i++) {
            int r = i * 8 + rbase;
            int gr = m0 + r;
            float4 v = make_float4(0.f, 0.f, 0.f, 0.f);
            float s = 1.0f;
            if (gr < M) {
                v = *(const float4*)(A + (size_t)gr * K + k0 + cq);
                if (scale) s = scale[gr];
            }
            v.x *= s; v.y *= s; v.z *= s; v.w *= s;
            __nv_bfloat16 hx = __float2bfloat16_rn(v.x);
            __nv_bfloat16 hy = __float2bfloat16_rn(v.y);
            __nv_bfloat16 hz = __float2bfloat16_rn(v.z);
            __nv_bfloat16 hw = __float2bfloat16_rn(v.w);
            __nv_bfloat16 lx = __float2bfloat16_rn(v.x - __bfloat162float(hx));
            __nv_bfloat16 ly = __float2bfloat16_rn(v.y - __bfloat162float(hy));
            __nv_bfloat16 lz = __float2bfloat16_rn(v.z - __bfloat162float(hz));
            __nv_bfloat16 lw = __float2bfloat16_rn(v.w - __bfloat162float(hw));
            uint2 hv = make_uint2(pack_bf(hx, hy), pack_bf(hz, hw));
            uint2 lv = make_uint2(pack_bf(lx, ly), pack_bf(lz, lw));
            uint32_t off = (uint32_t)(r * 128 + cq * 2);
            uint32_t so = off ^ ((off >> 3) & 0x70);
            *(uint2*)(smem + SM_AH + so) = hv;
            *(uint2*)(smem + SM_AL + so) = lv;
        }
        // ---- B tiles: pre-swizzled, straight copy ----
        {
            const uint4* sh = (const uint4*)(Bh + (size_t)kt * 32768);
            const uint4* sl = (const uint4*)(Bl + (size_t)kt * 32768);
            uint4* dh = (uint4*)(smem + SM_BH);
            uint4* dl = (uint4*)(smem + SM_BL);
            #pragma unroll
            for (int i = 0; i < 16; i++) {
                dh[tid + i * 128] = sh[tid + i * 128];
                dl[tid + i * 128] = sl[tid + i * 128];
            }
        }
        FENCE_ASYNC_SHARED();
        __syncthreads();
        // ---- MMA: D += Ahi*Bhi + Ahi*Blo + Alo*Bhi ----
        if (wid == 0) {
            if (elect_one_pred()) {
                #pragma unroll
                for (int sp = 0; sp < 3; sp++) {
                    uint64_t ad = (sp == 2) ? aL : aH;
                    uint64_t bd = (sp == 1) ? bL : bH;
                    #pragma unroll
                    for (int c = 0; c < 4; c++) {
                        uint32_t en = (kt == 0 && sp == 0 && c == 0) ? 0u : 1u;
                        mma_f16_ss(tmem,       ad + c * 2, bd + c * 2,        IDESC_G, en);
                        mma_f16_ss(tmem + 128, ad + c * 2, bd + 1024 + c * 2, IDESC_G, en);
                    }
                }
                TCGEN05_COMMIT(sb + SM_MBAR);
            }
        }
    }
    MBARRIER_WAIT_PARITY(sb + SM_MBAR, ph);
    TCGEN05_FENCE_AFTER();

    // ---- epilogue: TMEM -> GMEM fp32 ----
    int row = m0 + wid * 32 + lane;
    #pragma unroll
    for (int j = 0; j < 8; j++) {
        uint32_t r[32];
        TCGEN05_LD_X32(r, tmem + j * 32);
        TCGEN05_WAIT_LD();
        if (row < M) {
            float4* dst = (float4*)(C + (size_t)row * D_HID + j * 32);
            #pragma unroll
            for (int q = 0; q < 8; q++)
                dst[q] = make_float4(__uint_as_float(r[q * 4 + 0]), __uint_as_float(r[q * 4 + 1]),
                                     __uint_as_float(r[q * 4 + 2]), __uint_as_float(r[q * 4 + 3]));
        }
    }
    TCGEN05_FENCE_BEFORE();
    __syncthreads();
    if (tid == 0)
        asm volatile("mbarrier.inval.shared.b64 [%0];" :: "r"(sb + SM_MBAR) : "memory");
    __syncthreads();
    if (wid == 0) TCGEN05_DEALLOC(tmem, 256);
#else
    // Scalar fallback for the non-arch-specific PTX pass. Correct but slow;
    // never selected at runtime on GB300 (exact sm_103a cubin exists).
    int tid = threadIdx.x;
    int gr = blockIdx.x * 128 + tid;
    if (gr >= M) return;
    float s = scale ? scale[gr] : 1.0f;
    for (int n = 0; n < 256; n++) {
        float acc = 0.f;
        for (int k = 0; k < K; k++) {
            int kt = k >> 6, kk = k & 63;
            uint32_t off = (uint32_t)(n * 128 + kk * 2);
            off ^= ((off >> 3) & 0x70);
            float w = __bfloat162float(*(const __nv_bfloat16*)(Bh + (size_t)kt * 32768 + off))
                    + __bfloat162float(*(const __nv_bfloat16*)(Bl + (size_t)kt * 32768 + off));
            acc += A[(size_t)gr * K + k] * s * w;
        }
        C[(size_t)gr * 256 + n] = acc;
    }
#endif
}

// ---------------- zero kernels ----------------
__global__ void k_zero_nodes(unsigned* maxenc, float* denom) {
    int i = blockIdx.x * blockDim.x + threadIdx.x;
    if (i < N_NODES) { maxenc[i] = 0u; denom[i] = 0.0f; }
}
__global__ void k_zero_misc(float* bnsum, float* bnsq, float* pool, int* cnt) {
    int i = blockIdx.x * blockDim.x + threadIdx.x;
    if (i < N_GRAPHS * D_HID) pool[i] = 0.0f;
    if (i < D_HID) { bnsum[i] = 0.0f; bnsq[i] = 0.0f; }
    if (i < N_GRAPHS) cnt[i] = 0;
}
__global__ void k_zero_big(float4* p) {
    size_t i = (size_t)blockIdx.x * blockDim.x + threadIdx.x;
    if (i < (size_t)N_NODES * (D_HID / 4)) p[i] = make_float4(0.f, 0.f, 0.f, 0.f);
}

// ---------------- relevance (cosine) + graph counts ----------------
__global__ void k_rel(const float* __restrict__ claim, const float* __restrict__ x,
                      const int* __restrict__ batch, float* __restrict__ rel,
                      int* __restrict__ cnt) {
    int warp = (blockIdx.x * blockDim.x + threadIdx.x) >> 5;
    int lane = threadIdx.x & 31;
    if (warp >= N_NODES) return;
    int b = batch[warp];
    const float* ce = claim + (size_t)b * D_IN;
    const float* xv = x + (size_t)warp * D_IN;
    float dot = 0.f, nc = 0.f, nx = 0.f;
    #pragma unroll 4
    for (int k = lane; k < D_IN; k += 32) {
        float c = ce[k], v = xv[k];
        dot += c * v; nc += c * c; nx += v * v;
    }
    dot = warp_red(dot); nc = warp_red(nc); nx = warp_red(nx);
    if (lane == 0) {
        float nrm = sqrtf(nc) * sqrtf(nx);
        rel[warp] = dot / fmaxf(nrm, EPS_COS);
        atomicAdd(&cnt[b], 1);
    }
}

// ---------------- per-node attention coefficients ----------------
__global__ void k_alpha(const float* __restrict__ h,
                        const float* __restrict__ a_s, const float* __restrict__ a_d,
                        float* __restrict__ os, float* __restrict__ od) {
    int warp = (blockIdx.x * blockDim.x + threadIdx.x) >> 5;
    int lane = threadIdx.x & 31;
    if (warp >= N_NODES) return;
    const float* hr = h + (size_t)warp * D_HID;
    float s = 0.f, d = 0.f;
    #pragma unroll
    for (int j = lane; j < D_HID; j += 32) {
        float v = hr[j];
        s += v * a_s[j];
        d += v * a_d[j];
    }
    s = warp_red(s); d = warp_red(d);
    if (lane == 0) { os[warp] = s; od[warp] = d; }
}

// ---------------- edge pass 1: leaky-relu score + segment max ----------------
__global__ void k_edge_max(const int* __restrict__ ei,
                           const float* __restrict__ as, const float* __restrict__ ad,
                           float* __restrict__ edge, unsigned* __restrict__ maxenc) {
    int i = blockIdx.x * blockDim.x + threadIdx.x;
    if (i >= E_TOT) return;
    int s, d;
    if (i < N_EDGES) { s = ei[i]; d = ei[N_EDGES + i]; }
    else { s = d = i - N_EDGES; }
    float e = as[s] + ad[d];
    e = (e > 0.f) ? e : NEG_SLOPE * e;
    edge[i] = e;
    atomicMax(&maxenc[d], fenc(e));
}

// ---------------- edge pass 2: exp + segment sum ----------------
__global__ void k_edge_exp(const int* __restrict__ ei,
                           float* __restrict__ edge,
                           const unsigned* __restrict__ maxenc,
                           float* __restrict__ denom) {
    int i = blockIdx.x * blockDim.x + threadIdx.x;
    if (i >= E_TOT) return;
    int d = (i < N_EDGES) ? ei[N_EDGES + i] : (i - N_EDGES);
    float ex = expf(edge[i] - fdec(maxenc[d]));
    edge[i] = ex;
    atomicAdd(&denom[d], ex);
}

// ---------------- edge pass 3: weighted aggregation (warp/edge, v4 red) ----------------
__global__ void k_agg(const float* __restrict__ h, float* __restrict__ agg,
                      const int* __restrict__ ei, const float* __restrict__ edge,
                      const float* __restrict__ denom) {
    int i = (int)(((size_t)blockIdx.x * blockDim.x + threadIdx.x) >> 5);
    int lane = threadIdx.x & 31;
    if (i >= E_TOT) return;
    int s, d;
    if (i < N_EDGES) { s = ei[i]; d = ei[N_EDGES + i]; }
    else { s = d = i - N_EDGES; }
    float attn = edge[i] / denom[d];
    const float4* hs = (const float4*)(h + (size_t)s * D_HID);
    float4* od = (float4*)(agg + (size_t)d * D_HID);
    #pragma unroll
    for (int j = 0; j < 2; j++) {
        int c = lane + j * 32;
        float4 v = hs[c];
        asm volatile("red.global.add.v4.f32 [%0], {%1,%2,%3,%4};"
                     :: "l"(od + c),
                        "f"(v.x * attn), "f"(v.y * attn), "f"(v.z * attn), "f"(v.w * attn)
                     : "memory");
    }
}

// ---------------- BatchNorm stats ----------------
#define ROWS_PER_BLK 64
__global__ void k_bnstats(const float* __restrict__ h, float* __restrict__ bsum,
                          float* __restrict__ bsq) {
    int col = threadIdx.x;
    int r0 = blockIdx.x * ROWS_PER_BLK;
    int r1 = min(r0 + ROWS_PER_BLK, N_NODES);
    float s = 0.f, q = 0.f;
    for (int r = r0; r < r1; r++) {
        float v = h[(size_t)r * D_HID + col];
        s += v; q += v * v;
    }
    atomicAdd(&bsum[col], s);
    atomicAdd(&bsq[col], q);
}

// ---------------- BatchNorm apply + ReLU ----------------
__global__ void k_bnapply(const float* __restrict__ in, float* __restrict__ out,
                          const float* __restrict__ bsum, const float* __restrict__ bsq,
                          const float* __restrict__ gamma, const float* __restrict__ beta) {
    int col = threadIdx.x;
    float mu = bsum[col] * (1.0f / N_NODES);
    float var = bsq[col] * (1.0f / N_NODES) - mu * mu;
    float sc = gamma[col] * rsqrtf(var + EPS_BN);
    float sh = beta[col] - mu * sc;
    int r0 = blockIdx.x * ROWS_PER_BLK;
    int r1 = min(r0 + ROWS_PER_BLK, N_NODES);
    for (int r = r0; r < r1; r++) {
        float v = in[(size_t)r * D_HID + col];
        out[(size_t)r * D_HID + col] = fmaxf(v * sc + sh, 0.f);
    }
}

// ---------------- pool: relu(h + b2) summed per graph ----------------
__global__ void k_pool(const float* __restrict__ h, const float* __restrict__ b2,
                       const int* __restrict__ batch, float* __restrict__ pool) {
    int col = threadIdx.x;
    float bb = b2[col];
    int r0 = blockIdx.x * ROWS_PER_BLK;
    int r1 = min(r0 + ROWS_PER_BLK, N_NODES);
    int cur = -1;
    float acc = 0.f;
    for (int r = r0; r < r1; r++) {
        int g = batch[r];
        float v = fmaxf(h[(size_t)r * D_HID + col] + bb, 0.f);
        if (g != cur) {
            if (cur >= 0) atomicAdd(&pool[cur * D_HID + col], acc);
            cur = g; acc = v;
        } else acc += v;
    }
    if (cur >= 0) atomicAdd(&pool[cur * D_HID + col], acc);
}

// ---------------- classifier ----------------
__global__ void k_clf(const float* __restrict__ pool, const int* __restrict__ cnt,
                      const float* __restrict__ claim, const float* __restrict__ W,
                      const float* __restrict__ bias, float* __restrict__ out) {
    __shared__ float red[256];
    int b = blockIdx.x;
    int t = threadIdx.x;
    float c = fmaxf((float)cnt[b], 1.0f);
    float part = (pool[b * D_HID + t] / c) * W[t];
    #pragma unroll
    for (int j = 0; j < 3; j++) {
        int k = t + j * 256;
        part += claim[(size_t)b * D_IN + k] * W[D_HID + k];
    }
    red[t] = part;
    __syncthreads();
    #pragma unroll
    for (int o = 128; o; o >>= 1) {
        if (t < o) red[t] += red[t + o];
        __syncthreads();
    }
    if (t == 0) out[b] = red[0] + bias[0];
}

// ---------------- host launcher ----------------
extern "C" void kernel_launch(void* const* d_in, const int* in_sizes, int n_in,
                              void* d_out, int out_size) {
    const float* claim   = (const float*)d_in[0];
    const float* x       = (const float*)d_in[1];
    const int*   ei      = (const int*)d_in[2];
    const int*   batch   = (const int*)d_in[3];
    const float* W1      = (const float*)d_in[4];
    const float* a_src1  = (const float*)d_in[5];
    const float* a_dst1  = (const float*)d_in[6];
    // d_in[7] = b1 : provably no-op through training-mode BatchNorm
    const float* W2      = (const float*)d_in[8];
    const float* a_src2  = (const float*)d_in[9];
    const float* a_dst2  = (const float*)d_in[10];
    const float* b2      = (const float*)d_in[11];
    const float* gamma   = (const float*)d_in[12];
    const float* beta    = (const float*)d_in[13];
    const float* clfW    = (const float*)d_in[14];
    const float* clfb    = (const float*)d_in[15];
    float* out = (float*)d_out;

    float *p_rel, *p_A, *p_B, *p_as, *p_ad, *p_denom, *p_edge, *p_bnsum, *p_bnsq, *p_pool;
    unsigned* p_maxenc;
    int* p_cnt;
    unsigned char *p_w1h, *p_w1l, *p_w2h, *p_w2l;
    cudaGetSymbolAddress((void**)&p_rel, g_rel);
    cudaGetSymbolAddress((void**)&p_A, g_bufA);
    cudaGetSymbolAddress((void**)&p_B, g_bufB);
    cudaGetSymbolAddress((void**)&p_as, g_as);
    cudaGetSymbolAddress((void**)&p_ad, g_ad);
    cudaGetSymbolAddress((void**)&p_maxenc, g_maxenc);
    cudaGetSymbolAddress((void**)&p_denom, g_denom);
    cudaGetSymbolAddress((void**)&p_edge, g_edge);
    cudaGetSymbolAddress((void**)&p_bnsum, g_bnsum);
    cudaGetSymbolAddress((void**)&p_bnsq, g_bnsq);
    cudaGetSymbolAddress((void**)&p_pool, g_pool);
    cudaGetSymbolAddress((void**)&p_cnt, g_cnt);
    cudaGetSymbolAddress((void**)&p_w1h, g_w1h);
    cudaGetSymbolAddress((void**)&p_w1l, g_w1l);
    cudaGetSymbolAddress((void**)&p_w2h, g_w2h);
    cudaGetSymbolAddress((void**)&p_w2l, g_w2l);

    cudaFuncSetAttribute(k_gemm_tc, cudaFuncAttributeMaxDynamicSharedMemorySize, SM_SZ);

    const int nodeBlocks = (N_NODES + 255) / 256;
    const int edgeBlocks = (E_TOT + 255) / 256;
    const int warpNodeBlocks = (N_NODES * 32 + 255) / 256;
    const int warpEdgeBlocks = (int)(((size_t)E_TOT * 32 + 255) / 256);
    const int bigBlocks = (int)(((size_t)N_NODES * (D_HID / 4) + 255) / 256);
    const int chunkBlocks = (N_NODES + ROWS_PER_BLK - 1) / ROWS_PER_BLK;
    const int gemmBlocks = (N_NODES + 127) / 128;

    // ---- init + weight prep ----
    k_prep_w<<<(D_IN * 256 + 255) / 256, 256>>>(W1, D_IN, p_w1h, p_w1l);
    k_prep_w<<<(D_HID * 256 + 255) / 256, 256>>>(W2, D_HID, p_w2h, p_w2l);
    k_zero_nodes<<<nodeBlocks, 256>>>(p_maxenc, p_denom);
    k_zero_misc<<<(N_GRAPHS * D_HID + 255) / 256, 256>>>(p_bnsum, p_bnsq, p_pool, p_cnt);
    k_zero_big<<<bigBlocks, 256>>>((float4*)p_B);

    // ---- relevance scaling + counts ----
    k_rel<<<warpNodeBlocks, 256>>>(claim, x, batch, p_rel, p_cnt);

    // ---- layer 1: GAT ----
    k_gemm_tc<<<gemmBlocks, 128, SM_SZ>>>(x, D_IN, p_w1h, p_w1l, p_A, p_rel, N_NODES);
    k_alpha<<<warpNodeBlocks, 256>>>(p_A, a_src1, a_dst1, p_as, p_ad);
    k_edge_max<<<edgeBlocks, 256>>>(ei, p_as, p_ad, p_edge, p_maxenc);
    k_edge_exp<<<edgeBlocks, 256>>>(ei, p_edge, p_maxenc, p_denom);
    k_agg<<<warpEdgeBlocks, 256>>>(p_A, p_B, ei, p_edge, p_denom);

    // ---- BN + ReLU (b1 cancels exactly in training-mode BN) ----
    k_bnstats<<<chunkBlocks, 256>>>(p_B, p_bnsum, p_bnsq);
    k_bnapply<<<chunkBlocks, 256>>>(p_B, p_A, p_bnsum, p_bnsq, gamma, beta);

    // ---- layer 2: GAT ----
    k_gemm_tc<<<gemmBlocks, 128, SM_SZ>>>(p_A, D_HID, p_w2h, p_w2l, p_B, nullptr, N_NODES);
    k_alpha<<<warpNodeBlocks, 256>>>(p_B, a_src2, a_dst2, p_as, p_ad);
    k_zero_nodes<<<nodeBlocks, 256>>>(p_maxenc, p_denom);
    k_zero_big<<<bigBlocks, 256>>>((float4*)p_A);
    k_edge_max<<<edgeBlocks, 256>>>(ei, p_as, p_ad, p_edge, p_maxenc);
    k_edge_exp<<<edgeBlocks, 256>>>(ei, p_edge, p_maxenc, p_denom);
    k_agg<<<warpEdgeBlocks, 256>>>(p_B, p_A, ei, p_edge, p_denom);

    // ---- pool + classifier ----
    k_pool<<<chunkBlocks, 256>>>(p_A, b2, batch, p_pool);
    k_clf<<<N_GRAPHS, 256>>>(p_pool, p_cnt, claim, clfW, clfb, out);
}